// round 9
// baseline (speedup 1.0000x reference)
#include <cuda_runtime.h>
#include <cstdint>
#include <math.h>

using u64 = unsigned long long;

// Problem constants
constexpr int S = 4;
constexpr int T = 512;
constexpr int B = 16;
constexpr int D = 512;

constexpr int CPB    = 32;                 // blocks per batch
constexpr int ITERS  = T / CPB;            // 16 t-rows per block (perfectly even)
constexpr int NBLOCKS = CPB * B;           // 512 blocks, one wave at occ 4
constexpr int NACC   = 16;                 // 16 squared distances (sp*4+sg)

constexpr int NS         = 3;              // pipeline stages
constexpr int ROW_BYTES  = D * 4;          // 2048 B per (s,t) row
constexpr int STAGE_BYTES = 8 * ROW_BYTES; // 4 pred rows + 4 gt rows = 16 KB
constexpr int SMEM_BYTES = NS * STAGE_BYTES + NS * 16;  // data + (full,empty) pairs

// Deterministic scratch
__device__ float g_part[B][CPB][NACC];
__device__ int   g_done = 0;

// ---------------- PTX helpers ----------------
__device__ __forceinline__ uint32_t smem_u32(const void* p) {
    uint32_t a;
    asm("{ .reg .u64 t; cvta.to.shared.u64 t, %1; cvt.u32.u64 %0, t; }" : "=r"(a) : "l"(p));
    return a;
}
__device__ __forceinline__ void mbar_init(uint32_t a, uint32_t cnt) {
    asm volatile("mbarrier.init.shared.b64 [%0], %1;" :: "r"(a), "r"(cnt) : "memory");
}
__device__ __forceinline__ void mbar_expect_tx(uint32_t a, uint32_t bytes) {
    asm volatile("mbarrier.arrive.expect_tx.shared.b64 _, [%0], %1;" :: "r"(a), "r"(bytes) : "memory");
}
__device__ __forceinline__ void mbar_arrive(uint32_t a) {
    asm volatile("mbarrier.arrive.shared.b64 _, [%0];" :: "r"(a) : "memory");
}
__device__ __forceinline__ void mbar_wait(uint32_t a, uint32_t phase) {
    asm volatile(
        "{\n\t.reg .pred P;\n\t"
        "W_%=:\n\t"
        "mbarrier.try_wait.parity.acquire.cta.shared::cta.b64 P, [%0], %1, 0x989680;\n\t"
        "@P bra.uni DN_%=;\n\t"
        "bra.uni W_%=;\n\t"
        "DN_%=:\n\t}"
        :: "r"(a), "r"(phase) : "memory");
}
__device__ __forceinline__ void bulk_g2s(uint32_t dst, const void* src, uint32_t bytes, uint32_t mbar) {
    asm volatile(
        "cp.async.bulk.shared::cta.global.mbarrier::complete_tx::bytes [%0], [%1], %2, [%3];"
        :: "r"(dst), "l"(src), "r"(bytes), "r"(mbar) : "memory");
}
__device__ __forceinline__ void fence_async() {
    asm volatile("fence.proxy.async.shared::cta;" ::: "memory");
}
__device__ __forceinline__ u64 lds64(uint32_t a) {
    u64 v;
    asm volatile("ld.shared.b64 %0, [%1];" : "=l"(v) : "r"(a));
    return v;
}
__device__ __forceinline__ void fma2(u64& acc, u64 a, u64 b) {
    asm("fma.rn.f32x2 %0, %1, %2, %0;" : "+l"(acc) : "l"(a), "l"(b));
}
__device__ __forceinline__ u64 add2(u64 a, u64 b) {
    u64 r;
    asm("add.rn.f32x2 %0, %1, %2;" : "=l"(r) : "l"(a), "l"(b));
    return r;
}
__device__ __forceinline__ float unpack_sum(u64 v) {
    float lo, hi;
    asm("mov.b64 {%0, %1}, %2;" : "=f"(lo), "=f"(hi) : "l"(v));
    return lo + hi;
}

// Issue the 8 bulk copies (4 pred rows + 4 gt rows) for (b, t) into one stage.
__device__ __forceinline__ void produce(const float* __restrict__ preds,
                                        const float* __restrict__ gts,
                                        int b, int t, uint32_t stage, uint32_t fullbar)
{
    mbar_expect_tx(fullbar, STAGE_BYTES);
#pragma unroll
    for (int s = 0; s < 4; ++s) {
        bulk_g2s(stage + s * ROW_BYTES,
                 preds + ((size_t)(s * T + t) * B + b) * D, ROW_BYTES, fullbar);
        bulk_g2s(stage + (4 + s) * ROW_BYTES,
                 gts + ((size_t)(s * B + b) * T + t) * D, ROW_BYTES, fullbar);
    }
}

// ---------------------------------------------------------------------------
// Fused kernel: cp.async.bulk 3-stage pipeline, occ 4 (32 warps/SM).
// Block (cx, b): batch b, t in [cx*16, cx*16+16). Thread tid owns the float2
// at byte offset tid*8 of every 2KB row in the stage -> 8 x LDS.64 per iter,
// 16 add2 + 16 fma2 into packed f32x2 squared-distance accumulators.
// ---------------------------------------------------------------------------
__global__ __launch_bounds__(256, 4) void minloss_fused(
    const float* __restrict__ preds,   // [S, T, B, D]
    const float* __restrict__ gts,     // [S, B, T, D]
    float* __restrict__ out)
{
    extern __shared__ char smem[];
    const int b   = blockIdx.y;
    const int cx  = blockIdx.x;
    const int tid = threadIdx.x;

    const uint32_t sbase = smem_u32(smem);
    const uint32_t mb    = sbase + NS * STAGE_BYTES;   // full[s]@+16s, empty[s]@+16s+8

    if (tid == 0) {
#pragma unroll
        for (int s = 0; s < NS; ++s) {
            mbar_init(mb + s * 16, 1);        // full: 1 arrive (expect_tx) + tx bytes
            mbar_init(mb + s * 16 + 8, 256);  // empty: all threads arrive
        }
    }
    __syncthreads();

    const int t0 = cx * ITERS;
    if (tid == 0) {
        fence_async();                        // order mbarrier init before async proxy
#pragma unroll
        for (int k = 0; k < NS; ++k)
            produce(preds, gts, b, t0 + k, sbase + k * STAGE_BYTES, mb + k * 16);
    }

    constexpr u64 SIGN2 = 0x8000000080000000ull;
    u64 acc[NACC];
#pragma unroll
    for (int i = 0; i < NACC; ++i) acc[i] = 0ull;

    const uint32_t doff = tid * 8;
    int cs = 0;
    uint32_t cph = 0;

    for (int it = 0; it < ITERS; ++it) {
        const uint32_t st = sbase + cs * STAGE_BYTES + doff;
        mbar_wait(mb + cs * 16, cph);         // wait full

        u64 p[4], ng[4];
#pragma unroll
        for (int s = 0; s < 4; ++s) {
            p[s]  = lds64(st + s * ROW_BYTES);
            ng[s] = lds64(st + (4 + s) * ROW_BYTES) ^ SIGN2;   // -g
        }
#pragma unroll
        for (int sp = 0; sp < 4; ++sp)
#pragma unroll
            for (int sg = 0; sg < 4; ++sg) {
                u64 d = add2(p[sp], ng[sg]);                   // p - g
                fma2(acc[sp * 4 + sg], d, d);
            }

        mbar_arrive(mb + cs * 16 + 8);        // arrive empty (release: LDS done)

        if (tid == 0 && it + NS < ITERS) {
            mbar_wait(mb + cs * 16 + 8, cph); // all 256 consumed this stage
            fence_async();                    // generic reads before async write (WAR)
            produce(preds, gts, b, t0 + it + NS, sbase + cs * STAGE_BYTES, mb + cs * 16);
        }

        if (++cs == NS) { cs = 0; cph ^= 1; }
    }

    // ---------------- block reduction ----------------
    float vals[NACC];
#pragma unroll
    for (int i = 0; i < NACC; ++i) {
        vals[i] = unpack_sum(acc[i]);
#pragma unroll
        for (int off = 16; off > 0; off >>= 1)
            vals[i] += __shfl_down_sync(0xffffffffu, vals[i], off);
    }

    __shared__ float sacc[8][NACC];
    const int warp = tid >> 5;
    const int lane = tid & 31;
    if (lane == 0) {
#pragma unroll
        for (int i = 0; i < NACC; ++i) sacc[warp][i] = vals[i];
    }
    __syncthreads();

    if (tid < NACC) {
        float a = 0.0f;
#pragma unroll
        for (int w = 0; w < 8; ++w) a += sacc[w][tid];
        g_part[b][cx][tid] = a;               // deterministic overwrite
    }

    // ---- last-block ticket ----
    __threadfence();
    __syncthreads();
    __shared__ int s_last;
    if (tid == 0) {
        int ticket = atomicAdd(&g_done, 1);
        s_last = (ticket == NBLOCKS - 1);
    }
    __syncthreads();
    if (!s_last) return;

    // ================= Phase B (last block) =================
    __threadfence();                          // acquire

    __shared__ float s_final[B][NACC];
#pragma unroll
    for (int k = 0; k < 2; ++k) {
        const int bb = warp * 2 + k;
        if (lane < NACC) {
            float a = 0.0f;
#pragma unroll
            for (int cc = 0; cc < CPB; ++cc)
                a += __ldcg(&g_part[bb][cc][lane]);
            s_final[bb][lane] = a;
        }
    }
    __syncthreads();

    __shared__ float batch_total[B];
    if (tid < B) {
        const float* a = s_final[tid];
        float dist[16];
#pragma unroll
        for (int i = 0; i < 16; ++i)
            dist[i] = sqrtf(fmaxf(a[i], 0.0f));

        const float INF = __int_as_float(0x7f800000);
        float total = 0.0f;
#pragma unroll
        for (int it = 0; it < 4; ++it) {
            int   m    = 0;
            float best = dist[0];
#pragma unroll
            for (int k = 1; k < 16; ++k)
                if (dist[k] < best) { best = dist[k]; m = k; }   // first occurrence
            total += best;
            const int r = m >> 2, cc = m & 3;
#pragma unroll
            for (int k = 0; k < 4; ++k) {
                dist[r * 4 + k]  = INF;
                dist[k * 4 + cc] = INF;
            }
        }
        batch_total[tid] = total;
    }
    __syncthreads();

    if (tid == 0) {
        float s = 0.0f;
#pragma unroll
        for (int bb = 0; bb < B; ++bb) s += batch_total[bb];
        out[0] = s;
        g_done = 0;                           // reset for next graph replay
    }
}

extern "C" void kernel_launch(void* const* d_in, const int* in_sizes, int n_in,
                              void* d_out, int out_size)
{
    const float* preds = (const float*)d_in[0];  // [4, 512, 16, 512]
    const float* gts   = (const float*)d_in[1];  // [4, 16, 512, 512]
    float* out = (float*)d_out;

    cudaFuncSetAttribute(minloss_fused,
                         cudaFuncAttributeMaxDynamicSharedMemorySize, SMEM_BYTES);
    dim3 grid(CPB, B);                           // (32, 16) = 512 blocks
    minloss_fused<<<grid, 256, SMEM_BYTES>>>(preds, gts, out);
}